// round 1
// baseline (speedup 1.0000x reference)
#include <cuda_runtime.h>
#include <cuda_bf16.h>
#include <math.h>

// ConvEncoder: y[b,s,o] = GELU( sum_{k<5,e<128} emb[x[b,s+k-2]][e] * W[o][k*128+e] + bias[o] )
// B=16, S=2048, EMB=128, WIN=5, OUT=128, fan_in=640.
//
// Implemented as a smem-tiled GEMM: M=32768 tokens, N=128, K=640.
// Each CTA: 128 tokens x 128 outs. The A operand (im2col) is materialized
// implicitly: one halo'd embedding tile (132 rows x 128) covers all 5 K-chunks
// via a row shift. W is staged per-K-chunk transposed to [k][out] in smem.
// Accumulation uses Blackwell packed fp32 FMA (fma.rn.f32x2) to double
// fp32 FMA throughput vs scalar FFMA.

#define CE_B    16
#define CE_S    2048
#define CE_EMB  128
#define CE_WIN  5
#define CE_OUT  128
#define CE_KTOT 640
#define CE_MT   128     // tokens per CTA
#define CE_HALO 2

#define FMA_F32X2(d, a, b, c) \
    asm("fma.rn.f32x2 %0, %1, %2, %3;" : "=l"(d) : "l"(a), "l"(b), "l"(c))

#define PACK_AA(out, f) \
    asm("mov.b64 %0, {%1, %1};" : "=l"(out) : "f"(f))

#define UNPACK2(lo, hi, v) \
    asm("mov.b64 {%0, %1}, %2;" : "=f"(lo), "=f"(hi) : "l"(v))

__device__ __forceinline__ float gelu_exact(float y) {
    return 0.5f * y * (1.0f + erff(y * 0.70710678118654752f));
}

__global__ void __launch_bounds__(256, 1)
conv_encoder_kernel(const int* __restrict__ x,
                    const float* __restrict__ emb,
                    const float* __restrict__ W,
                    const float* __restrict__ bias,
                    float* __restrict__ out)
{
    extern __shared__ float smem[];
    float* Ae = smem;                          // [CE_MT+4][128]  (132*128 floats)
    float* Bw = smem + (CE_MT + 4) * CE_EMB;   // [128 kk][128 out]

    const int tid   = threadIdx.x;
    const int batch = blockIdx.y;
    const int s0    = blockIdx.x * CE_MT;

    // ---- Load halo'd embedding tile: rows p=0..131 correspond to seq s0+p-2 ----
    {
        const int* xrow = x + batch * CE_S;
        float4* Ae4 = reinterpret_cast<float4*>(Ae);
        #pragma unroll
        for (int it = 0; it < (CE_MT + 4) * (CE_EMB / 4) / 256; ++it) {
            int idx = tid + it * 256;                  // 132*32 = 4224 tasks; 16.5/thread
            int p = idx >> 5;
            int c = idx & 31;
            int s = s0 + p - CE_HALO;
            float4 v = make_float4(0.f, 0.f, 0.f, 0.f);
            if (s >= 0 && s < CE_S) {
                int tok = xrow[s];
                v = *reinterpret_cast<const float4*>(emb + (size_t)tok * CE_EMB + c * 4);
            }
            Ae4[idx] = v;
        }
        // remainder (4224 = 16*256 + 128)
        {
            int idx = tid + 16 * 256;
            if (idx < (CE_MT + 4) * (CE_EMB / 4)) {
                int p = idx >> 5;
                int c = idx & 31;
                int s = s0 + p - CE_HALO;
                float4 v = make_float4(0.f, 0.f, 0.f, 0.f);
                if (s >= 0 && s < CE_S) {
                    int tok = xrow[s];
                    v = *reinterpret_cast<const float4*>(emb + (size_t)tok * CE_EMB + c * 4);
                }
                Ae4[idx] = v;
            }
        }
    }

    const int row_blk = tid >> 4;   // 0..15 -> token group of 8
    const int col_blk = tid & 15;   // 0..15 -> out group of 8
    const int cb8 = col_blk * 8;

    unsigned long long acc[8][4];
    #pragma unroll
    for (int i = 0; i < 8; ++i)
        #pragma unroll
        for (int j = 0; j < 4; ++j)
            acc[i][j] = 0ULL;

    // ---- K-chunk loop: kc selects window offset; A row shift = kc ----
    for (int kc = 0; kc < CE_WIN; ++kc) {
        if (kc) __syncthreads();   // previous chunk's readers done before overwrite

        // Stage W chunk transposed: Bw[kk][out] = W[out][kc*128 + kk]
        // 128 out x 32 float4 = 4096 tasks, 16/thread. Lanes vary 'out' ->
        // smem stores conflict-free.
        #pragma unroll
        for (int it = 0; it < 16; ++it) {
            int idx = tid + it * 256;
            int o  = idx & 127;
            int kq = idx >> 7;     // 0..31
            float4 w = *reinterpret_cast<const float4*>(
                W + (size_t)o * CE_KTOT + kc * CE_EMB + kq * 4);
            Bw[(kq * 4 + 0) * CE_OUT + o] = w.x;
            Bw[(kq * 4 + 1) * CE_OUT + o] = w.y;
            Bw[(kq * 4 + 2) * CE_OUT + o] = w.z;
            Bw[(kq * 4 + 3) * CE_OUT + o] = w.w;
        }
        __syncthreads();

        const float* Abase = Ae + (row_blk * 8 + kc) * CE_EMB;

        #pragma unroll 4
        for (int kk = 0; kk < CE_EMB; ++kk) {
            const float* brow = Bw + kk * CE_OUT + cb8;
            ulonglong2 bq0 = *reinterpret_cast<const ulonglong2*>(brow);
            ulonglong2 bq1 = *reinterpret_cast<const ulonglong2*>(brow + 4);
            #pragma unroll
            for (int i = 0; i < 8; ++i) {
                float a = Abase[i * CE_EMB + kk];
                unsigned long long aa;
                PACK_AA(aa, a);
                FMA_F32X2(acc[i][0], aa, bq0.x, acc[i][0]);
                FMA_F32X2(acc[i][1], aa, bq0.y, acc[i][1]);
                FMA_F32X2(acc[i][2], aa, bq1.x, acc[i][2]);
                FMA_F32X2(acc[i][3], aa, bq1.y, acc[i][3]);
            }
        }
    }

    // ---- Epilogue: bias + exact GELU + store ----
    float bvals[8];
    {
        float4 b0 = *reinterpret_cast<const float4*>(bias + cb8);
        float4 b1 = *reinterpret_cast<const float4*>(bias + cb8 + 4);
        bvals[0] = b0.x; bvals[1] = b0.y; bvals[2] = b0.z; bvals[3] = b0.w;
        bvals[4] = b1.x; bvals[5] = b1.y; bvals[6] = b1.z; bvals[7] = b1.w;
    }

    #pragma unroll
    for (int i = 0; i < 8; ++i) {
        int s = s0 + row_blk * 8 + i;            // always < CE_S (MT divides S)
        float y[8];
        #pragma unroll
        for (int j = 0; j < 4; ++j) {
            float lo, hi;
            UNPACK2(lo, hi, acc[i][j]);
            y[2 * j]     = gelu_exact(lo + bvals[2 * j]);
            y[2 * j + 1] = gelu_exact(hi + bvals[2 * j + 1]);
        }
        float* orow = out + ((size_t)(batch * CE_S + s) * CE_OUT) + cb8;
        *reinterpret_cast<float4*>(orow)     = make_float4(y[0], y[1], y[2], y[3]);
        *reinterpret_cast<float4*>(orow + 4) = make_float4(y[4], y[5], y[6], y[7]);
    }
}

extern "C" void kernel_launch(void* const* d_in, const int* in_sizes, int n_in,
                              void* d_out, int out_size)
{
    const int*   x    = (const int*)  d_in[0];
    const float* emb  = (const float*)d_in[1];
    const float* W    = (const float*)d_in[2];
    const float* bias = (const float*)d_in[3];
    float*       out  = (float*)d_out;

    const size_t smem_bytes = ((CE_MT + 4) * CE_EMB + CE_EMB * CE_OUT) * sizeof(float);
    cudaFuncSetAttribute(conv_encoder_kernel,
                         cudaFuncAttributeMaxDynamicSharedMemorySize,
                         (int)smem_bytes);

    dim3 grid(CE_S / CE_MT, CE_B);   // 16 x 16 = 256 CTAs
    conv_encoder_kernel<<<grid, 256, smem_bytes>>>(x, emb, W, bias, out);
}

// round 3
// speedup vs baseline: 2.2155x; 2.2155x over previous
#include <cuda_runtime.h>
#include <cuda_bf16.h>
#include <math.h>
#include <stdint.h>

// ConvEncoder as mma.sync (HMMA) bf16 split-precision GEMM.
// y[b,s,o] = GELU( sum_{kc<5,e<128} emb[x[b,s+kc-2]][e] * W[o][kc*128+e] + b[o] )
// GEMM: M=32768 tokens, N=128 outs, K=640.
// Precision: v = v_hi + v_lo (bf16 split); D += AhWh + AhWl + AlWh (err ~2^-17).
// NOTE: tcgen05 is unavailable (harness lowers via .target sm_103, no 'a'),
// so we use mma.sync.m16n8k16.bf16 which is baseline sm_80+ PTX.

#define CE_S    2048
#define CE_KTOT 640
#define THREADS 256

// smem: rows padded to 272 B (68 words) -> bank = (68*r + c) % 32 = 4r + c,
// conflict-free for all fragment load patterns below.
#define ROW_B   272
#define SM_A_HI 0
#define SM_A_LO (128 * ROW_B)           // 34816
#define SM_W_HI (2 * 128 * ROW_B)       // 69632
#define SM_W_LO (3 * 128 * ROW_B)       // 104448
#define SM_BIAS (4 * 128 * ROW_B)       // 139264
#define SM_TOT  (SM_BIAS + 512)         // 139776

__device__ __forceinline__ float gelu_exact(float y) {
    return 0.5f * y * (1.0f + erff(y * 0.70710678118654752f));
}

__device__ __forceinline__ void mma_bf16(float* c, const uint32_t* a, const uint32_t* b) {
    asm volatile(
        "mma.sync.aligned.m16n8k16.row.col.f32.bf16.bf16.f32 "
        "{%0,%1,%2,%3}, {%4,%5,%6,%7}, {%8,%9}, {%0,%1,%2,%3};"
        : "+f"(c[0]), "+f"(c[1]), "+f"(c[2]), "+f"(c[3])
        : "r"(a[0]), "r"(a[1]), "r"(a[2]), "r"(a[3]), "r"(b[0]), "r"(b[1]));
}

// split one float4 into bf16 hi / lo packed pairs
__device__ __forceinline__ void split4(float4 v, uint2* hi, uint2* lo) {
    union { __nv_bfloat16 h[4]; uint2 u; } ph, pl;
    float f[4] = {v.x, v.y, v.z, v.w};
    #pragma unroll
    for (int j = 0; j < 4; ++j) {
        __nv_bfloat16 hb = __float2bfloat16(f[j]);
        ph.h[j] = hb;
        pl.h[j] = __float2bfloat16(f[j] - __bfloat162float(hb));
    }
    *hi = ph.u;
    *lo = pl.u;
}

__global__ void __launch_bounds__(THREADS)
conv_encoder_hmma(const int* __restrict__ x,
                  const float* __restrict__ emb,
                  const float* __restrict__ W,
                  const float* __restrict__ bias,
                  float* __restrict__ out)
{
    extern __shared__ uint8_t smem[];
    const int tid = threadIdx.x;
    const int wid = tid >> 5;
    const int lid = tid & 31;
    const int g   = lid >> 2;       // 0..7
    const int q   = lid & 3;        // 0..3
    const int wm  = wid >> 2;       // 0..1  (64-row band)
    const int wn  = wid & 3;        // 0..3  (32-col band)
    const int batch = blockIdx.y;
    const int s0 = blockIdx.x * 128;
    const int* xrow = x + batch * CE_S;

    if (tid < 32) {
        reinterpret_cast<float4*>(smem + SM_BIAS)[tid] =
            reinterpret_cast<const float4*>(bias)[tid];
    }

    float acc[4][4][4];   // [m-tile][n-tile][frag]
    #pragma unroll
    for (int i = 0; i < 4; ++i)
        #pragma unroll
        for (int j = 0; j < 4; ++j)
            #pragma unroll
            for (int r = 0; r < 4; ++r)
                acc[i][j][r] = 0.f;

    for (int kc = 0; kc < 5; ++kc) {
        if (kc) __syncthreads();    // previous chunk's readers done

        // ---- stage A chunk: rows p=0..127 <- emb[x[s0+p+kc-2]], bf16 hi/lo ----
        #pragma unroll
        for (int it = 0; it < 16; ++it) {
            int idx = tid + it * THREADS;   // 128 rows x 32 float4
            int p = idx >> 5;
            int c = idx & 31;
            int s = s0 + p + kc - 2;
            float4 v = make_float4(0.f, 0.f, 0.f, 0.f);
            if (s >= 0 && s < CE_S)
                v = *reinterpret_cast<const float4*>(emb + (size_t)xrow[s] * 128 + c * 4);
            uint2 hi, lo;
            split4(v, &hi, &lo);
            *reinterpret_cast<uint2*>(smem + SM_A_HI + p * ROW_B + c * 8) = hi;
            *reinterpret_cast<uint2*>(smem + SM_A_LO + p * ROW_B + c * 8) = lo;
        }
        // ---- stage W chunk: rows o=0..127, k = kc*128.. , bf16 hi/lo ----
        #pragma unroll
        for (int it = 0; it < 16; ++it) {
            int idx = tid + it * THREADS;
            int o = idx >> 5;
            int c = idx & 31;
            float4 v = *reinterpret_cast<const float4*>(
                W + (size_t)o * CE_KTOT + kc * 128 + c * 4);
            uint2 hi, lo;
            split4(v, &hi, &lo);
            *reinterpret_cast<uint2*>(smem + SM_W_HI + o * ROW_B + c * 8) = hi;
            *reinterpret_cast<uint2*>(smem + SM_W_LO + o * ROW_B + c * 8) = lo;
        }
        __syncthreads();

        // ---- 8 k-steps of 16 over this chunk; 3 fused precision passes ----
        #pragma unroll
        for (int ks = 0; ks < 8; ++ks) {
            const int kb = ks * 32 + q * 4;   // byte offset of this thread's k pair

            uint32_t Ah[4][4], Al[4][4], Bh[4][2], Bl[4][2];
            #pragma unroll
            for (int i = 0; i < 4; ++i) {
                int r0 = (wm * 64 + i * 16 + g) * ROW_B + kb;
                int r1 = r0 + 8 * ROW_B;
                Ah[i][0] = *reinterpret_cast<const uint32_t*>(smem + SM_A_HI + r0);
                Ah[i][1] = *reinterpret_cast<const uint32_t*>(smem + SM_A_HI + r1);
                Ah[i][2] = *reinterpret_cast<const uint32_t*>(smem + SM_A_HI + r0 + 16);
                Ah[i][3] = *reinterpret_cast<const uint32_t*>(smem + SM_A_HI + r1 + 16);
                Al[i][0] = *reinterpret_cast<const uint32_t*>(smem + SM_A_LO + r0);
                Al[i][1] = *reinterpret_cast<const uint32_t*>(smem + SM_A_LO + r1);
                Al[i][2] = *reinterpret_cast<const uint32_t*>(smem + SM_A_LO + r0 + 16);
                Al[i][3] = *reinterpret_cast<const uint32_t*>(smem + SM_A_LO + r1 + 16);
            }
            #pragma unroll
            for (int j = 0; j < 4; ++j) {
                int o0 = (wn * 32 + j * 8 + g) * ROW_B + kb;
                Bh[j][0] = *reinterpret_cast<const uint32_t*>(smem + SM_W_HI + o0);
                Bh[j][1] = *reinterpret_cast<const uint32_t*>(smem + SM_W_HI + o0 + 16);
                Bl[j][0] = *reinterpret_cast<const uint32_t*>(smem + SM_W_LO + o0);
                Bl[j][1] = *reinterpret_cast<const uint32_t*>(smem + SM_W_LO + o0 + 16);
            }
            #pragma unroll
            for (int i = 0; i < 4; ++i)
                #pragma unroll
                for (int j = 0; j < 4; ++j) {
                    mma_bf16(acc[i][j], Ah[i], Bh[j]);
                    mma_bf16(acc[i][j], Ah[i], Bl[j]);
                    mma_bf16(acc[i][j], Al[i], Bh[j]);
                }
        }
    }

    // ---- epilogue: bias + exact GELU + store ----
    const float* bs = reinterpret_cast<const float*>(smem + SM_BIAS);
    #pragma unroll
    for (int i = 0; i < 4; ++i) {
        int row0 = s0 + wm * 64 + i * 16 + g;
        #pragma unroll
        for (int j = 0; j < 4; ++j) {
            int col = wn * 32 + j * 8 + q * 2;
            float b0 = bs[col], b1 = bs[col + 1];
            float2 v0, v1;
            v0.x = gelu_exact(acc[i][j][0] + b0);
            v0.y = gelu_exact(acc[i][j][1] + b1);
            v1.x = gelu_exact(acc[i][j][2] + b0);
            v1.y = gelu_exact(acc[i][j][3] + b1);
            float* p0 = out + ((size_t)(batch * CE_S + row0)) * 128 + col;
            *reinterpret_cast<float2*>(p0) = v0;
            *reinterpret_cast<float2*>(p0 + 8 * 128) = v1;
        }
    }
}

extern "C" void kernel_launch(void* const* d_in, const int* in_sizes, int n_in,
                              void* d_out, int out_size)
{
    const int*   x    = (const int*)  d_in[0];
    const float* emb  = (const float*)d_in[1];
    const float* W    = (const float*)d_in[2];
    const float* bias = (const float*)d_in[3];
    float*       out  = (float*)d_out;

    cudaFuncSetAttribute(conv_encoder_hmma,
                         cudaFuncAttributeMaxDynamicSharedMemorySize, SM_TOT);

    dim3 grid(CE_S / 128, 16);   // 16 x 16 = 256 CTAs
    conv_encoder_hmma<<<grid, THREADS, SM_TOT>>>(x, emb, W, bias, out);
}

// round 4
// speedup vs baseline: 2.6250x; 1.1848x over previous
#include <cuda_runtime.h>
#include <cuda_bf16.h>
#include <math.h>
#include <stdint.h>

// ConvEncoder: y = GELU(im2col(emb[x]) @ W^T + b).  M=32768, N=128, K=640.
// mma.sync m16n8k16 bf16, split precision: D += AhWh + AhWl + AlWh (~2^-17 err).
// R4: A halo staged once per CTA (window shift = row offset), W pre-converted
// to bf16 hi/lo by a prep kernel and double-buffered via cp.async, fragments
// loaded with ldmatrix.

#define CE_S    2048
#define CE_KTOT 640
#define THREADS 256
#define ROW_B   272                  // 256B bf16 row + 16B pad (odd 16B stride)

// smem layout (bytes)
#define SA_HI   0
#define SA_LO   35904                // 132 * 272
#define SW_BASE 71808                // 2 bufs x (hi 34816 + lo 34816)
#define SW_BUF  69632
#define SW_LO   34816
#define SBIAS   211072
#define SM_TOT  211584

// W pre-converted: [h(2)][kc(5)][o(128)][272B]
__device__ __align__(16) unsigned char g_Wcvt[2 * 5 * 128 * ROW_B];

__device__ __forceinline__ float gelu_exact(float y) {
    return 0.5f * y * (1.0f + erff(y * 0.70710678118654752f));
}

__device__ __forceinline__ void mma_bf16(float* c, const uint32_t* a, const uint32_t* b) {
    asm volatile(
        "mma.sync.aligned.m16n8k16.row.col.f32.bf16.bf16.f32 "
        "{%0,%1,%2,%3}, {%4,%5,%6,%7}, {%8,%9}, {%0,%1,%2,%3};"
        : "+f"(c[0]), "+f"(c[1]), "+f"(c[2]), "+f"(c[3])
        : "r"(a[0]), "r"(a[1]), "r"(a[2]), "r"(a[3]), "r"(b[0]), "r"(b[1]));
}

__device__ __forceinline__ void ldsm4(uint32_t* r, uint32_t addr) {
    asm volatile("ldmatrix.sync.aligned.m8n8.x4.shared.b16 {%0,%1,%2,%3}, [%4];"
                 : "=r"(r[0]), "=r"(r[1]), "=r"(r[2]), "=r"(r[3]) : "r"(addr));
}

__device__ __forceinline__ void ldsm2(uint32_t* r, uint32_t addr) {
    asm volatile("ldmatrix.sync.aligned.m8n8.x2.shared.b16 {%0,%1}, [%2];"
                 : "=r"(r[0]), "=r"(r[1]) : "r"(addr));
}

__device__ __forceinline__ void cpasync16(uint32_t dst, const void* src) {
    asm volatile("cp.async.cg.shared.global [%0], [%1], 16;"
                 :: "r"(dst), "l"(src) : "memory");
}

__device__ __forceinline__ void split4(float4 v, uint2* hi, uint2* lo) {
    union { __nv_bfloat16 h[4]; uint2 u; } ph, pl;
    float f[4] = {v.x, v.y, v.z, v.w};
    #pragma unroll
    for (int j = 0; j < 4; ++j) {
        __nv_bfloat16 hb = __float2bfloat16(f[j]);
        ph.h[j] = hb;
        pl.h[j] = __float2bfloat16(f[j] - __bfloat162float(hb));
    }
    *hi = ph.u;
    *lo = pl.u;
}

// ---- prep: W f32 -> bf16 hi/lo, chunked layout for direct cp.async ----
__global__ void __launch_bounds__(256)
prep_w_kernel(const float* __restrict__ W)
{
    int t = blockIdx.x * 256 + threadIdx.x;        // 5*128*16 = 10240 granules
    if (t >= 5 * 128 * 16) return;
    int gnl = t & 15;
    int o   = (t >> 4) & 127;
    int kc  = t >> 11;
    const float* src = W + (size_t)o * CE_KTOT + kc * 128 + gnl * 8;
    float4 v0 = *reinterpret_cast<const float4*>(src);
    float4 v1 = *reinterpret_cast<const float4*>(src + 4);
    uint2 h0, l0, h1, l1;
    split4(v0, &h0, &l0);
    split4(v1, &h1, &l1);
    size_t off_hi = ((size_t)(0 * 5 + kc) * 128 + o) * ROW_B + gnl * 16;
    size_t off_lo = ((size_t)(1 * 5 + kc) * 128 + o) * ROW_B + gnl * 16;
    *reinterpret_cast<uint4*>(g_Wcvt + off_hi) = make_uint4(h0.x, h0.y, h1.x, h1.y);
    *reinterpret_cast<uint4*>(g_Wcvt + off_lo) = make_uint4(l0.x, l0.y, l1.x, l1.y);
}

// issue cp.async for one W chunk (hi+lo) into smem buffer
__device__ __forceinline__ void stage_w(uint32_t sw, int kc, int tid) {
    const unsigned char* bh = g_Wcvt + (size_t)(0 * 5 + kc) * 128 * ROW_B;
    const unsigned char* bl = g_Wcvt + (size_t)(1 * 5 + kc) * 128 * ROW_B;
    #pragma unroll
    for (int it = 0; it < 8; ++it) {
        int idx = tid + it * THREADS;              // 2048: o x 16 granules
        int o = idx >> 4, gnl = idx & 15;
        uint32_t d = sw + o * ROW_B + gnl * 16;
        size_t so = (size_t)o * ROW_B + gnl * 16;
        cpasync16(d, bh + so);
        cpasync16(d + SW_LO, bl + so);
    }
}

__global__ void __launch_bounds__(THREADS)
conv_encoder_hmma(const int* __restrict__ x,
                  const float* __restrict__ emb,
                  const float* __restrict__ bias,
                  float* __restrict__ out)
{
    extern __shared__ uint8_t smem[];
    uint32_t sb;
    asm("{ .reg .u64 t; cvta.to.shared.u64 t, %1; cvt.u32.u64 %0, t; }"
        : "=r"(sb) : "l"(smem));

    const int tid = threadIdx.x;
    const int wid = tid >> 5;
    const int lid = tid & 31;
    const int g   = lid >> 2;
    const int q   = lid & 3;
    const int wm  = wid >> 2;       // 0..1
    const int wn  = wid & 3;        // 0..3
    const int batch = blockIdx.y;
    const int s0 = blockIdx.x * 128;
    const int* xrow = x + batch * CE_S;

    // prefetch W chunk 0 immediately (overlaps with A gather below)
    stage_w(sb + SW_BASE, 0, tid);
    asm volatile("cp.async.commit_group;" ::: "memory");

    if (tid < 32) {
        reinterpret_cast<float4*>(smem + SBIAS)[tid] =
            reinterpret_cast<const float4*>(bias)[tid];
    }

    // ---- stage halo'd A once: rows p=0..131 -> seq s0+p-2, bf16 hi/lo ----
    #pragma unroll
    for (int it = 0; it < 17; ++it) {
        int idx = tid + it * THREADS;              // 132*32 float4 tasks
        if (idx < 132 * 32) {
            int p = idx >> 5;
            int c = idx & 31;
            int s = s0 + p - 2;
            float4 v = make_float4(0.f, 0.f, 0.f, 0.f);
            if (s >= 0 && s < CE_S)
                v = *reinterpret_cast<const float4*>(emb + (size_t)xrow[s] * 128 + c * 4);
            uint2 hi, lo;
            split4(v, &hi, &lo);
            *reinterpret_cast<uint2*>(smem + SA_HI + p * ROW_B + c * 8) = hi;
            *reinterpret_cast<uint2*>(smem + SA_LO + p * ROW_B + c * 8) = lo;
        }
    }

    float acc[4][4][4];
    #pragma unroll
    for (int i = 0; i < 4; ++i)
        #pragma unroll
        for (int j = 0; j < 4; ++j)
            #pragma unroll
            for (int r = 0; r < 4; ++r)
                acc[i][j][r] = 0.f;

    // per-lane ldmatrix offsets
    const uint32_t a_off = ((lid & 7) + ((lid >> 3) & 1) * 8) * ROW_B + (lid >> 4) * 16;
    const uint32_t b_off = (lid & 7) * ROW_B + ((lid >> 3) & 1) * 16;

    for (int kc = 0; kc < 5; ++kc) {
        if (kc < 4) {
            stage_w(sb + SW_BASE + ((kc + 1) & 1) * SW_BUF, kc + 1, tid);
            asm volatile("cp.async.commit_group;" ::: "memory");
            asm volatile("cp.async.wait_group 1;" ::: "memory");
        } else {
            asm volatile("cp.async.wait_group 0;" ::: "memory");
        }
        __syncthreads();

        const uint32_t swb = sb + SW_BASE + (kc & 1) * SW_BUF;
        const uint32_t aA  = sb + (wm * 64 + kc) * ROW_B + a_off;
        const uint32_t aB  = swb + wn * 32 * ROW_B + b_off;

        #pragma unroll
        for (int ks = 0; ks < 8; ++ks) {
            const uint32_t kb = ks * 32;
            uint32_t Ah[4][4], Al[4][4], Bh[4][2], Bl[4][2];
            #pragma unroll
            for (int i = 0; i < 4; ++i) {
                ldsm4(Ah[i], aA + SA_HI + i * (16 * ROW_B) + kb);
                ldsm4(Al[i], aA + SA_LO + i * (16 * ROW_B) + kb);
            }
            #pragma unroll
            for (int j = 0; j < 4; ++j) {
                ldsm2(Bh[j], aB + j * (8 * ROW_B) + kb);
                ldsm2(Bl[j], aB + SW_LO + j * (8 * ROW_B) + kb);
            }
            #pragma unroll
            for (int i = 0; i < 4; ++i)
                #pragma unroll
                for (int j = 0; j < 4; ++j) {
                    mma_bf16(acc[i][j], Ah[i], Bh[j]);
                    mma_bf16(acc[i][j], Ah[i], Bl[j]);
                    mma_bf16(acc[i][j], Al[i], Bh[j]);
                }
        }
        __syncthreads();   // MMA readers done before next chunk's cp.async lands
    }

    // ---- epilogue: bias + exact GELU + store ----
    const float* bs = reinterpret_cast<const float*>(smem + SBIAS);
    #pragma unroll
    for (int i = 0; i < 4; ++i) {
        int row0 = s0 + wm * 64 + i * 16 + g;
        #pragma unroll
        for (int j = 0; j < 4; ++j) {
            int col = wn * 32 + j * 8 + q * 2;
            float b0 = bs[col], b1 = bs[col + 1];
            float2 v0, v1;
            v0.x = gelu_exact(acc[i][j][0] + b0);
            v0.y = gelu_exact(acc[i][j][1] + b1);
            v1.x = gelu_exact(acc[i][j][2] + b0);
            v1.y = gelu_exact(acc[i][j][3] + b1);
            float* p0 = out + ((size_t)(batch * CE_S + row0)) * 128 + col;
            *reinterpret_cast<float2*>(p0) = v0;
            *reinterpret_cast<float2*>(p0 + 8 * 128) = v1;
        }
    }
}

extern "C" void kernel_launch(void* const* d_in, const int* in_sizes, int n_in,
                              void* d_out, int out_size)
{
    const int*   x    = (const int*)  d_in[0];
    const float* emb  = (const float*)d_in[1];
    const float* W    = (const float*)d_in[2];
    const float* bias = (const float*)d_in[3];
    float*       out  = (float*)d_out;

    prep_w_kernel<<<40, 256>>>(W);

    cudaFuncSetAttribute(conv_encoder_hmma,
                         cudaFuncAttributeMaxDynamicSharedMemorySize, SM_TOT);
    dim3 grid(CE_S / 128, 16);   // 256 CTAs
    conv_encoder_hmma<<<grid, THREADS, SM_TOT>>>(x, emb, bias, out);
}

// round 5
// speedup vs baseline: 2.7437x; 1.0452x over previous
#include <cuda_runtime.h>
#include <cuda_bf16.h>
#include <math.h>
#include <stdint.h>

// ConvEncoder: y = GELU(im2col(emb[x]) @ W^T + b).  M=32768, N=128, K=640.
// mma.sync m16n8k16 bf16, split precision: D += AhWh + AhWl + AlWh (~2^-17 err).
// R5: 512 threads (4 warps/SMSP), 256 tokens/CTA -> 128 CTAs = 1 wave,
// W streamed as 10 K=64 sub-chunks double-buffered via cp.async.

#define CE_S    2048
#define CE_KTOT 640
#define THREADS 512
#define TOK     256
#define ROW_B   272                  // A smem row stride (256B data + 16B pad)
#define WROW    144                  // W smem row stride (128B data + 16B pad)

// smem layout (bytes)
#define SA_HI   0
#define SA_LO   70720                // 260 * 272
#define SW_BASE 141440               // 2 bufs x (hi 18432 + lo 18432)
#define SW_BUF  36864
#define SW_LO   18432
#define SBIAS   215168
#define SM_TOT  215680

// W pre-converted: [h(2)][kc(5)][o(128)][272B]
__device__ __align__(16) unsigned char g_Wcvt[2 * 5 * 128 * ROW_B];

__device__ __forceinline__ float gelu_exact(float y) {
    return 0.5f * y * (1.0f + erff(y * 0.70710678118654752f));
}

__device__ __forceinline__ void mma_bf16(float* c, const uint32_t* a, const uint32_t* b) {
    asm volatile(
        "mma.sync.aligned.m16n8k16.row.col.f32.bf16.bf16.f32 "
        "{%0,%1,%2,%3}, {%4,%5,%6,%7}, {%8,%9}, {%0,%1,%2,%3};"
        : "+f"(c[0]), "+f"(c[1]), "+f"(c[2]), "+f"(c[3])
        : "r"(a[0]), "r"(a[1]), "r"(a[2]), "r"(a[3]), "r"(b[0]), "r"(b[1]));
}

__device__ __forceinline__ void ldsm4(uint32_t* r, uint32_t addr) {
    asm volatile("ldmatrix.sync.aligned.m8n8.x4.shared.b16 {%0,%1,%2,%3}, [%4];"
                 : "=r"(r[0]), "=r"(r[1]), "=r"(r[2]), "=r"(r[3]) : "r"(addr));
}

__device__ __forceinline__ void ldsm2(uint32_t* r, uint32_t addr) {
    asm volatile("ldmatrix.sync.aligned.m8n8.x2.shared.b16 {%0,%1}, [%2];"
                 : "=r"(r[0]), "=r"(r[1]) : "r"(addr));
}

__device__ __forceinline__ void cpasync16(uint32_t dst, const void* src) {
    asm volatile("cp.async.cg.shared.global [%0], [%1], 16;"
                 :: "r"(dst), "l"(src) : "memory");
}

__device__ __forceinline__ void split4(float4 v, uint2* hi, uint2* lo) {
    union { __nv_bfloat16 h[4]; uint2 u; } ph, pl;
    float f[4] = {v.x, v.y, v.z, v.w};
    #pragma unroll
    for (int j = 0; j < 4; ++j) {
        __nv_bfloat16 hb = __float2bfloat16(f[j]);
        ph.h[j] = hb;
        pl.h[j] = __float2bfloat16(f[j] - __bfloat162float(hb));
    }
    *hi = ph.u;
    *lo = pl.u;
}

// ---- prep: W f32 -> bf16 hi/lo, chunked layout for direct cp.async ----
__global__ void __launch_bounds__(256)
prep_w_kernel(const float* __restrict__ W)
{
    int t = blockIdx.x * 256 + threadIdx.x;        // 5*128*16 = 10240 granules
    if (t >= 5 * 128 * 16) return;
    int gnl = t & 15;
    int o   = (t >> 4) & 127;
    int kc  = t >> 11;
    const float* src = W + (size_t)o * CE_KTOT + kc * 128 + gnl * 8;
    float4 v0 = *reinterpret_cast<const float4*>(src);
    float4 v1 = *reinterpret_cast<const float4*>(src + 4);
    uint2 h0, l0, h1, l1;
    split4(v0, &h0, &l0);
    split4(v1, &h1, &l1);
    size_t off_hi = ((size_t)(0 * 5 + kc) * 128 + o) * ROW_B + gnl * 16;
    size_t off_lo = ((size_t)(1 * 5 + kc) * 128 + o) * ROW_B + gnl * 16;
    *reinterpret_cast<uint4*>(g_Wcvt + off_hi) = make_uint4(h0.x, h0.y, h1.x, h1.y);
    *reinterpret_cast<uint4*>(g_Wcvt + off_lo) = make_uint4(l0.x, l0.y, l1.x, l1.y);
}

// stage one K=64 sub-chunk (hi+lo) into smem buffer via cp.async
__device__ __forceinline__ void stage_w(uint32_t swdst, int sub, int tid) {
    const int kc    = sub >> 1;
    const int khalf = sub & 1;
    const unsigned char* bh = g_Wcvt + (size_t)(0 * 5 + kc) * 128 * ROW_B;
    const unsigned char* bl = g_Wcvt + (size_t)(1 * 5 + kc) * 128 * ROW_B;
    #pragma unroll
    for (int it = 0; it < 2; ++it) {
        int idx = tid + it * THREADS;              // 128 o x 8 granules
        int o = idx >> 3, gnl = idx & 7;
        uint32_t d = swdst + o * WROW + gnl * 16;
        size_t so = (size_t)o * ROW_B + khalf * 128 + gnl * 16;
        cpasync16(d, bh + so);
        cpasync16(d + SW_LO, bl + so);
    }
}

__global__ void __launch_bounds__(THREADS, 1)
conv_encoder_hmma(const int* __restrict__ x,
                  const float* __restrict__ emb,
                  const float* __restrict__ bias,
                  float* __restrict__ out)
{
    extern __shared__ uint8_t smem[];
    uint32_t sb;
    asm("{ .reg .u64 t; cvta.to.shared.u64 t, %1; cvt.u32.u64 %0, t; }"
        : "=r"(sb) : "l"(smem));

    const int tid = threadIdx.x;
    const int wid = tid >> 5;
    const int lid = tid & 31;
    const int g   = lid >> 2;
    const int q   = lid & 3;
    const int wm  = wid >> 2;       // 0..3  (64-row band within 256)
    const int wn  = wid & 3;        // 0..3  (32-col band)
    const int batch = blockIdx.y;
    const int s0 = blockIdx.x * TOK;
    const int* xrow = x + batch * CE_S;

    // prefetch first two W sub-chunks (overlap with A gather)
    stage_w(sb + SW_BASE, 0, tid);
    asm volatile("cp.async.commit_group;" ::: "memory");
    stage_w(sb + SW_BASE + SW_BUF, 1, tid);
    asm volatile("cp.async.commit_group;" ::: "memory");

    if (tid < 32) {
        reinterpret_cast<float4*>(smem + SBIAS)[tid] =
            reinterpret_cast<const float4*>(bias)[tid];
    }

    // ---- stage halo'd A once: rows p=0..259 -> seq s0+p-2, bf16 hi/lo ----
    #pragma unroll
    for (int it = 0; it < 17; ++it) {
        int idx = tid + it * THREADS;              // 260*32 = 8320 float4 tasks
        if (idx < 260 * 32) {
            int p = idx >> 5;
            int c = idx & 31;
            int s = s0 + p - 2;
            float4 v = make_float4(0.f, 0.f, 0.f, 0.f);
            if (s >= 0 && s < CE_S)
                v = *reinterpret_cast<const float4*>(emb + (size_t)xrow[s] * 128 + c * 4);
            uint2 hi, lo;
            split4(v, &hi, &lo);
            *reinterpret_cast<uint2*>(smem + SA_HI + p * ROW_B + c * 8) = hi;
            *reinterpret_cast<uint2*>(smem + SA_LO + p * ROW_B + c * 8) = lo;
        }
    }

    float acc[4][4][4];
    #pragma unroll
    for (int i = 0; i < 4; ++i)
        #pragma unroll
        for (int j = 0; j < 4; ++j)
            #pragma unroll
            for (int r = 0; r < 4; ++r)
                acc[i][j][r] = 0.f;

    // per-lane ldmatrix offsets
    const uint32_t a_off = ((lid & 7) + ((lid >> 3) & 1) * 8) * ROW_B + (lid >> 4) * 16;
    const uint32_t b_off = (lid & 7) * WROW + ((lid >> 3) & 1) * 16;

    // ---- 10 sub-chunks of K=64, double-buffered ----
    for (int s = 0; s < 10; ++s) {
        if (s < 9) {
            asm volatile("cp.async.wait_group 1;" ::: "memory");
        } else {
            asm volatile("cp.async.wait_group 0;" ::: "memory");
        }
        __syncthreads();

        const int kc    = s >> 1;
        const uint32_t kbase = (uint32_t)((s & 1) * 128);
        const uint32_t swb = sb + SW_BASE + (s & 1) * SW_BUF;
        const uint32_t aA  = sb + (wm * 64 + kc) * ROW_B + a_off + kbase;
        const uint32_t aB  = swb + wn * 32 * WROW + b_off;

        #pragma unroll
        for (int ks = 0; ks < 4; ++ks) {
            const uint32_t kb = ks * 32;
            uint32_t Ah[4][4], Al[4][4], Bh[4][2], Bl[4][2];
            #pragma unroll
            for (int i = 0; i < 4; ++i) {
                ldsm4(Ah[i], aA + SA_HI + i * (16 * ROW_B) + kb);
                ldsm4(Al[i], aA + SA_LO + i * (16 * ROW_B) + kb);
            }
            #pragma unroll
            for (int j = 0; j < 4; ++j) {
                ldsm2(Bh[j], aB + j * (8 * WROW) + kb);
                ldsm2(Bl[j], aB + SW_LO + j * (8 * WROW) + kb);
            }
            #pragma unroll
            for (int i = 0; i < 4; ++i)
                #pragma unroll
                for (int j = 0; j < 4; ++j) {
                    mma_bf16(acc[i][j], Ah[i], Bh[j]);
                    mma_bf16(acc[i][j], Ah[i], Bl[j]);
                    mma_bf16(acc[i][j], Al[i], Bh[j]);
                }
        }
        __syncthreads();   // readers done before buffer reuse
        if (s < 8) {
            stage_w(sb + SW_BASE + (s & 1) * SW_BUF, s + 2, tid);
            asm volatile("cp.async.commit_group;" ::: "memory");
        }
    }

    // ---- epilogue: bias + exact GELU + store ----
    const float* bs = reinterpret_cast<const float*>(smem + SBIAS);
    #pragma unroll
    for (int i = 0; i < 4; ++i) {
        int row0 = s0 + wm * 64 + i * 16 + g;
        #pragma unroll
        for (int j = 0; j < 4; ++j) {
            int col = wn * 32 + j * 8 + q * 2;
            float b0 = bs[col], b1 = bs[col + 1];
            float2 v0, v1;
            v0.x = gelu_exact(acc[i][j][0] + b0);
            v0.y = gelu_exact(acc[i][j][1] + b1);
            v1.x = gelu_exact(acc[i][j][2] + b0);
            v1.y = gelu_exact(acc[i][j][3] + b1);
            float* p0 = out + ((size_t)(batch * CE_S + row0)) * 128 + col;
            *reinterpret_cast<float2*>(p0) = v0;
            *reinterpret_cast<float2*>(p0 + 8 * 128) = v1;
        }
    }
}

extern "C" void kernel_launch(void* const* d_in, const int* in_sizes, int n_in,
                              void* d_out, int out_size)
{
    const int*   x    = (const int*)  d_in[0];
    const float* emb  = (const float*)d_in[1];
    const float* W    = (const float*)d_in[2];
    const float* bias = (const float*)d_in[3];
    float*       out  = (float*)d_out;

    prep_w_kernel<<<40, 256>>>(W);

    cudaFuncSetAttribute(conv_encoder_hmma,
                         cudaFuncAttributeMaxDynamicSharedMemorySize, SM_TOT);
    dim3 grid(CE_S / TOK, 16);   // 8 x 16 = 128 CTAs (one wave)
    conv_encoder_hmma<<<grid, THREADS, SM_TOT>>>(x, emb, bias, out);
}